// round 3
// baseline (speedup 1.0000x reference)
#include <cuda_runtime.h>

// ----------------------------------------------------------------------------
// TemporalEmbedding: out[o,b,l,:] = emb0[i0]@W0 + emb1[i1]@W1 + emb2[i2]@W2
//                                   + (pe[l]@W3 + b)
// Strategy: precompute tiny per-source tables (1.24 GFLOP total), then a
// memory-bound gather-add writing the 268 MB output.
// ----------------------------------------------------------------------------

#define DMODEL 512
#define BATCH  32
#define PLEN   2048

// Scratch tables (static device allocation — allowed; no runtime alloc).
__device__ float g_T0[7    * DMODEL];
__device__ float g_T1[24   * DMODEL];
__device__ float g_T2[288  * DMODEL];
__device__ float g_Tp[PLEN * DMODEL];

// ----------------------------------------------------------------------------
// Kernel 1: tiled SGEMM computing all four tables in one launch.
// grid.x enumerates (segment, m-tile): 1 + 1 + 5 + 32 = 39 ; grid.y = 8 n-tiles.
// Block tile 64x64, K-tile 16, 256 threads, 4x4 register tile per thread.
// ----------------------------------------------------------------------------
__global__ __launch_bounds__(256, 4) void table_gemm(
    const float* __restrict__ emb0, const float* __restrict__ emb1,
    const float* __restrict__ emb2, const float* __restrict__ pe,
    const float* __restrict__ W,    const float* __restrict__ bias)
{
    int bx = blockIdx.x;
    const int by = blockIdx.y;

    const float* A; float* C; int M, koff; bool addb = false;
    if (bx < 1)      { A = emb0; C = g_T0; M = 7;    koff = 0;              }
    else if (bx < 2) { A = emb1; C = g_T1; M = 24;   koff = 512;  bx -= 1;  }
    else if (bx < 7) { A = emb2; C = g_T2; M = 288;  koff = 1024; bx -= 2;  }
    else             { A = pe;   C = g_Tp; M = PLEN; koff = 1536; bx -= 7; addb = true; }

    const int row0 = bx * 64;
    const int col0 = by * 64;

    __shared__ float As[16][64];   // [k][m]
    __shared__ float Bs[16][64];   // [k][n]

    const int tid = threadIdx.x;
    // A-load mapping: 64 rows x 4 float4 (16 k) per tile
    const int am = tid >> 2, aq = tid & 3;
    // B-load mapping: 16 k-rows x 16 float4 (64 n)
    const int bk = tid >> 4, bq = tid & 15;
    // compute mapping: 16x16 threads, each 4x4 outputs
    const int tx = tid & 15, ty = tid >> 4;

    const bool avalid = (row0 + am) < M;
    const float* Ap = A + (size_t)(row0 + am) * DMODEL + aq * 4;
    const float* Bp = W + (size_t)(koff + bk) * DMODEL + col0 + bq * 4;

    float acc[4][4] = {};

    const float4 z4 = make_float4(0.f, 0.f, 0.f, 0.f);
    float4 a4 = avalid ? *(const float4*)(Ap) : z4;
    float4 b4 = *(const float4*)(Bp);

    for (int k0 = 0; k0 < DMODEL; k0 += 16) {
        As[aq * 4 + 0][am] = a4.x;
        As[aq * 4 + 1][am] = a4.y;
        As[aq * 4 + 2][am] = a4.z;
        As[aq * 4 + 3][am] = a4.w;
        *(float4*)&Bs[bk][bq * 4] = b4;
        __syncthreads();

        if (k0 + 16 < DMODEL) {   // software prefetch next K-tile
            a4 = avalid ? *(const float4*)(Ap + k0 + 16) : z4;
            b4 = *(const float4*)(Bp + (size_t)(k0 + 16) * DMODEL);
        }

        #pragma unroll
        for (int k = 0; k < 16; k++) {
            float4 av = *(const float4*)&As[k][ty * 4];
            float4 bv = *(const float4*)&Bs[k][tx * 4];
            float ar[4] = {av.x, av.y, av.z, av.w};
            float br[4] = {bv.x, bv.y, bv.z, bv.w};
            #pragma unroll
            for (int i = 0; i < 4; i++)
                #pragma unroll
                for (int j = 0; j < 4; j++)
                    acc[i][j] += ar[i] * br[j];
        }
        __syncthreads();
    }

    float bb[4] = {0.f, 0.f, 0.f, 0.f};
    if (addb) {
        bb[0] = bias[col0 + tx * 4 + 0];
        bb[1] = bias[col0 + tx * 4 + 1];
        bb[2] = bias[col0 + tx * 4 + 2];
        bb[3] = bias[col0 + tx * 4 + 3];
    }

    #pragma unroll
    for (int i = 0; i < 4; i++) {
        int r = row0 + ty * 4 + i;
        if (r < M) {
            float4 v;
            v.x = acc[i][0] + bb[0];
            v.y = acc[i][1] + bb[1];
            v.z = acc[i][2] + bb[2];
            v.w = acc[i][3] + bb[3];
            *(float4*)&C[(size_t)r * DMODEL + col0 + tx * 4] = v;
        }
    }
}

// ----------------------------------------------------------------------------
// Kernel 2: gather-add. grid (2048 l-positions, 2 outputs), 128 threads.
// Each thread owns one float4 of the 512-dim vector; Tp[l] is loaded once and
// reused across all 32 batch rows. Output stored with streaming hint (__stcs)
// so the 268 MB write stream does not evict the L2-resident tables.
// ----------------------------------------------------------------------------
__global__ __launch_bounds__(128) void gather_add(
    const int* __restrict__ in0, const int* __restrict__ tg0,
    const int* __restrict__ in1, const int* __restrict__ tg1,
    const int* __restrict__ in2, const int* __restrict__ tg2,
    float* __restrict__ out)
{
    const int l = blockIdx.x;
    const int o = blockIdx.y;
    const int t = threadIdx.x;            // float4 lane within d-dim (0..127)

    __shared__ int sidx[3][BATCH];
    if (t < 96) {
        int which = t >> 5;               // 0,1,2 -> vocab stream
        int b     = t & 31;
        const int* p = (which == 0) ? (o ? tg0 : in0)
                     : (which == 1) ? (o ? tg1 : in1)
                                    : (o ? tg2 : in2);
        sidx[which][b] = p[b * PLEN + l];
    }
    __syncthreads();

    const float4* __restrict__ T0 = (const float4*)g_T0;
    const float4* __restrict__ T1 = (const float4*)g_T1;
    const float4* __restrict__ T2 = (const float4*)g_T2;
    const float4* __restrict__ Tp = (const float4*)g_Tp;

    const int NV4 = DMODEL / 4;           // 128
    const float4 tp = Tp[l * NV4 + t];

    float4* o4 = (float4*)out + ((size_t)o * BATCH * PLEN + l) * NV4 + t;

    #pragma unroll 4
    for (int b = 0; b < BATCH; b++) {
        const int i0 = sidx[0][b];
        const int i1 = sidx[1][b];
        const int i2 = sidx[2][b];
        float4 a = T0[i0 * NV4 + t];
        float4 c = T1[i1 * NV4 + t];
        float4 d = T2[i2 * NV4 + t];
        float4 v;
        v.x = tp.x + a.x + c.x + d.x;
        v.y = tp.y + a.y + c.y + d.y;
        v.z = tp.z + a.z + c.z + d.z;
        v.w = tp.w + a.w + c.w + d.w;
        __stcs(o4 + (size_t)b * PLEN * NV4, v);
    }
}

// ----------------------------------------------------------------------------
// Launch. Inputs per metadata order:
//  0:in0 1:tg0 2:in1 3:tg1 4:in2 5:tg2 (int32 [32,2048])
//  6:emb0 [7,512] 7:emb1 [24,512] 8:emb2 [288,512]
//  9:pe [4096,512] 10:W [2048,512] 11:b [512]    output: float32 [2,32,2048,512]
// ----------------------------------------------------------------------------
extern "C" void kernel_launch(void* const* d_in, const int* in_sizes, int n_in,
                              void* d_out, int out_size)
{
    const int*   in0  = (const int*)  d_in[0];
    const int*   tg0  = (const int*)  d_in[1];
    const int*   in1  = (const int*)  d_in[2];
    const int*   tg1  = (const int*)  d_in[3];
    const int*   in2  = (const int*)  d_in[4];
    const int*   tg2  = (const int*)  d_in[5];
    const float* emb0 = (const float*)d_in[6];
    const float* emb1 = (const float*)d_in[7];
    const float* emb2 = (const float*)d_in[8];
    const float* pe   = (const float*)d_in[9];
    const float* W    = (const float*)d_in[10];
    const float* bias = (const float*)d_in[11];
    float* out = (float*)d_out;

    dim3 g1(39, 8);          // 1+1+5+32 m-tiles x 8 n-tiles
    table_gemm<<<g1, 256>>>(emb0, emb1, emb2, pe, W, bias);

    dim3 g2(PLEN, 2);
    gather_add<<<g2, 128>>>(in0, tg0, in1, tg1, in2, tg2, out);
}

// round 5
// speedup vs baseline: 1.0435x; 1.0435x over previous
#include <cuda_runtime.h>

// ----------------------------------------------------------------------------
// TemporalEmbedding:
//   out[o,b,l,:] = emb0[i0]@W0 + emb1[i1]@W1 + emb2[i2]@W2 + (pe[l]@W3 + b)
// Three launches:
//   1) table_gemm : per-source tables (620M FMA total, FFMA-bound)
//   2) combine01  : T01[i,j] = T0[i] + T1[j]  (168x512, trivial)
//   3) gather_add : out = T01[i01] + T2[i2] + Tp[l]  (memory-bound, 268 MB)
// ----------------------------------------------------------------------------

#define DMODEL 512
#define BATCH  32
#define PLEN   2048
#define NV4    (DMODEL / 4)      // 128 float4 lanes per row
#define KTILE  16

// Static device scratch (no runtime allocation).
__device__ float g_T0 [7    * DMODEL];
__device__ float g_T1 [24   * DMODEL];
__device__ float g_T2 [288  * DMODEL];
__device__ float g_Tp [PLEN * DMODEL];
__device__ float g_T01[168  * DMODEL];   // 7*24 combined

// ----------------------------------------------------------------------------
// Kernel 1: tiled SGEMM for all four tables.
// 64x64 block tile, 128 threads, 8x4 register microtile, double-buffered smem.
// grid.x = 1(T0) + 1(T1) + 5(T2) + 32(Tp) = 39 m-tiles ; grid.y = 8 n-tiles.
// ----------------------------------------------------------------------------
__global__ __launch_bounds__(128, 6) void table_gemm(
    const float* __restrict__ emb0, const float* __restrict__ emb1,
    const float* __restrict__ emb2, const float* __restrict__ pe,
    const float* __restrict__ W,    const float* __restrict__ bias)
{
    int bx = blockIdx.x;
    const int by = blockIdx.y;

    const float* A; float* C; int M, koff; bool addb = false;
    if (bx < 1)      { A = emb0; C = g_T0; M = 7;    koff = 0;              }
    else if (bx < 2) { A = emb1; C = g_T1; M = 24;   koff = 512;  bx -= 1;  }
    else if (bx < 7) { A = emb2; C = g_T2; M = 288;  koff = 1024; bx -= 2;  }
    else             { A = pe;   C = g_Tp; M = PLEN; koff = 1536; bx -= 7; addb = true; }

    const int row0 = bx * 64;
    const int col0 = by * 64;

    __shared__ float As[2][KTILE][64];   // [buf][k][m]
    __shared__ float Bs[2][KTILE][64];   // [buf][k][n]

    const int tid = threadIdx.x;

    // A loader: 2 threads/row, each two float4 in k (8 k-values)
    const int am = tid >> 1;             // 0..63
    const int kq = (tid & 1) * 8;        // 0 or 8
    // B loader: 8 threads/row, each two float4 in n (8 n-values)
    const int bk = tid >> 3;             // 0..15
    const int bq = (tid & 7) * 8;        // 0,8,...,56
    // compute map: thread = 8 m-rows x 4 n-cols
    const int tx = tid & 15;             // n: tx*4
    const int ty = tid >> 4;             // m: ty*8

    const bool avalid = (row0 + am) < M;
    const float* Ap = A + (size_t)(row0 + am) * DMODEL;          // +k
    const float* Bp = W + (size_t)(koff + bk) * DMODEL + col0;   // +k0*DMODEL

    const float4 z4 = make_float4(0.f, 0.f, 0.f, 0.f);
    float4 a0, a1, b0, b1;

    // preload tile 0
    a0 = avalid ? *(const float4*)(Ap + kq)     : z4;
    a1 = avalid ? *(const float4*)(Ap + kq + 4) : z4;
    b0 = *(const float4*)(Bp + bq);
    b1 = *(const float4*)(Bp + bq + 4);

    // store tile 0 into buf 0 (A transposed to [k][m])
    As[0][kq + 0][am] = a0.x;  As[0][kq + 1][am] = a0.y;
    As[0][kq + 2][am] = a0.z;  As[0][kq + 3][am] = a0.w;
    As[0][kq + 4][am] = a1.x;  As[0][kq + 5][am] = a1.y;
    As[0][kq + 6][am] = a1.z;  As[0][kq + 7][am] = a1.w;
    *(float4*)&Bs[0][bk][bq]     = b0;
    *(float4*)&Bs[0][bk][bq + 4] = b1;
    __syncthreads();

    float acc[8][4] = {};

    const int NT = DMODEL / KTILE;   // 32
    for (int t = 0; t < NT; t++) {
        const int cur = t & 1;

        if (t + 1 < NT) {            // prefetch next K-tile into registers
            const int k0 = (t + 1) * KTILE;
            a0 = avalid ? *(const float4*)(Ap + k0 + kq)     : z4;
            a1 = avalid ? *(const float4*)(Ap + k0 + kq + 4) : z4;
            b0 = *(const float4*)(Bp + (size_t)k0 * DMODEL + bq);
            b1 = *(const float4*)(Bp + (size_t)k0 * DMODEL + bq + 4);
        }

        #pragma unroll
        for (int k = 0; k < KTILE; k++) {
            float4 av0 = *(const float4*)&As[cur][k][ty * 8];
            float4 av1 = *(const float4*)&As[cur][k][ty * 8 + 4];
            float4 bv  = *(const float4*)&Bs[cur][k][tx * 4];
            float ar[8] = {av0.x, av0.y, av0.z, av0.w, av1.x, av1.y, av1.z, av1.w};
            float br[4] = {bv.x, bv.y, bv.z, bv.w};
            #pragma unroll
            for (int i = 0; i < 8; i++)
                #pragma unroll
                for (int j = 0; j < 4; j++)
                    acc[i][j] += ar[i] * br[j];
        }

        if (t + 1 < NT) {            // stage prefetched tile into other buffer
            const int nx = cur ^ 1;
            As[nx][kq + 0][am] = a0.x;  As[nx][kq + 1][am] = a0.y;
            As[nx][kq + 2][am] = a0.z;  As[nx][kq + 3][am] = a0.w;
            As[nx][kq + 4][am] = a1.x;  As[nx][kq + 5][am] = a1.y;
            As[nx][kq + 6][am] = a1.z;  As[nx][kq + 7][am] = a1.w;
            *(float4*)&Bs[nx][bk][bq]     = b0;
            *(float4*)&Bs[nx][bk][bq + 4] = b1;
        }
        __syncthreads();
    }

    float bb[4] = {0.f, 0.f, 0.f, 0.f};
    if (addb) {
        bb[0] = bias[col0 + tx * 4 + 0];
        bb[1] = bias[col0 + tx * 4 + 1];
        bb[2] = bias[col0 + tx * 4 + 2];
        bb[3] = bias[col0 + tx * 4 + 3];
    }

    #pragma unroll
    for (int i = 0; i < 8; i++) {
        const int r = row0 + ty * 8 + i;
        if (r < M) {
            float4 v;
            v.x = acc[i][0] + bb[0];
            v.y = acc[i][1] + bb[1];
            v.z = acc[i][2] + bb[2];
            v.w = acc[i][3] + bb[3];
            *(float4*)&C[(size_t)r * DMODEL + col0 + tx * 4] = v;
        }
    }
}

// ----------------------------------------------------------------------------
// Kernel 2: T01[i*24+j] = T0[i] + T1[j].  grid=168, 128 threads (one float4 each).
// ----------------------------------------------------------------------------
__global__ __launch_bounds__(128) void combine01()
{
    const int r = blockIdx.x;            // 0..167
    const int t = threadIdx.x;           // 0..127
    const int i = r / 24;
    const int j = r % 24;
    const float4* T0 = (const float4*)g_T0;
    const float4* T1 = (const float4*)g_T1;
    float4 a = T0[i * NV4 + t];
    float4 b = T1[j * NV4 + t];
    float4 v;
    v.x = a.x + b.x;  v.y = a.y + b.y;  v.z = a.z + b.z;  v.w = a.w + b.w;
    ((float4*)g_T01)[r * NV4 + t] = v;
}

// ----------------------------------------------------------------------------
// Kernel 3: gather-add. grid (2048 l, 2 outputs), 128 threads (one float4 lane).
// 3 L1 accesses + 1 store per output float4 (was 5). Tp held in a register
// across all 32 batch rows; streaming stores keep tables L2-resident.
// ----------------------------------------------------------------------------
__global__ __launch_bounds__(128) void gather_add(
    const int* __restrict__ in0, const int* __restrict__ tg0,
    const int* __restrict__ in1, const int* __restrict__ tg1,
    const int* __restrict__ in2, const int* __restrict__ tg2,
    float* __restrict__ out)
{
    const int l = blockIdx.x;
    const int o = blockIdx.y;
    const int t = threadIdx.x;

    __shared__ int sidx[3][BATCH];
    if (t < 96) {
        int which = t >> 5;
        int b     = t & 31;
        const int* p = (which == 0) ? (o ? tg0 : in0)
                     : (which == 1) ? (o ? tg1 : in1)
                                    : (o ? tg2 : in2);
        sidx[which][b] = p[b * PLEN + l];
    }
    __syncthreads();

    const float4* __restrict__ T01 = (const float4*)g_T01;
    const float4* __restrict__ T2  = (const float4*)g_T2;
    const float4* __restrict__ Tp  = (const float4*)g_Tp;

    const float4 tp = Tp[l * NV4 + t];

    float4* o4 = (float4*)out + ((size_t)o * BATCH * PLEN + l) * NV4 + t;

    #pragma unroll 4
    for (int b = 0; b < BATCH; b++) {
        const int i01 = sidx[0][b] * 24 + sidx[1][b];
        const int i2  = sidx[2][b];
        float4 a = T01[i01 * NV4 + t];
        float4 d = T2 [i2  * NV4 + t];
        float4 v;
        v.x = tp.x + a.x + d.x;
        v.y = tp.y + a.y + d.y;
        v.z = tp.z + a.z + d.z;
        v.w = tp.w + a.w + d.w;
        __stcs(o4 + (size_t)b * PLEN * NV4, v);
    }
}

// ----------------------------------------------------------------------------
// Launch. Inputs (metadata order):
//  0..5: in0,tg0,in1,tg1,in2,tg2  int32 [32,2048]
//  6:emb0[7,512] 7:emb1[24,512] 8:emb2[288,512] 9:pe[4096,512]
//  10:W[2048,512] 11:b[512]        output: float32 [2,32,2048,512]
// ----------------------------------------------------------------------------
extern "C" void kernel_launch(void* const* d_in, const int* in_sizes, int n_in,
                              void* d_out, int out_size)
{
    const int*   in0  = (const int*)  d_in[0];
    const int*   tg0  = (const int*)  d_in[1];
    const int*   in1  = (const int*)  d_in[2];
    const int*   tg1  = (const int*)  d_in[3];
    const int*   in2  = (const int*)  d_in[4];
    const int*   tg2  = (const int*)  d_in[5];
    const float* emb0 = (const float*)d_in[6];
    const float* emb1 = (const float*)d_in[7];
    const float* emb2 = (const float*)d_in[8];
    const float* pe   = (const float*)d_in[9];
    const float* W    = (const float*)d_in[10];
    const float* bias = (const float*)d_in[11];
    float* out = (float*)d_out;

    dim3 g1(39, 8);
    table_gemm<<<g1, 128>>>(emb0, emb1, emb2, pe, W, bias);

    combine01<<<168, 128>>>();

    dim3 g3(PLEN, 2);
    gather_add<<<g3, 128>>>(in0, tg0, in1, tg1, in2, tg2, out);
}

// round 10
// speedup vs baseline: 1.2521x; 1.1999x over previous
#include <cuda_runtime.h>
#include <cuda_bf16.h>
#include <cstdint>

// ----------------------------------------------------------------------------
// TemporalEmbedding via precomputed tables.
//   out[o,b,l,:] = T01[i0*24+i1] + T2[i2] + Tp[l]
// Tables computed with Ampere-style mma.sync bf16 split-precision (3-term):
//   A@B ~= Ahi@Bhi + Ahi@Blo + Alo@Bhi   (fp32 accumulate)
// No tcgen05 (not available under this build's compute_103 target).
// Launch order: conv_W, conv_A, table_mma, combine01, gather_add.
// ----------------------------------------------------------------------------

#define DMODEL 512
#define BATCH  32
#define PLEN   2048
#define NV4    (DMODEL / 4)

// padded A rows: [0,2048) pe | [2048,2432) emb2 | [2432,2560) emb1 | [2560,2688) emb0
#define APAD   2688

__device__ float g_T0 [7    * DMODEL];
__device__ float g_T1 [24   * DMODEL];
__device__ float g_T2 [288  * DMODEL];
__device__ float g_Tp [PLEN * DMODEL];
__device__ float g_T01[168  * DMODEL];
__device__ __nv_bfloat16 g_Ahi[APAD * DMODEL];
__device__ __nv_bfloat16 g_Alo[APAD * DMODEL];
__device__ __nv_bfloat16 g_Whi[DMODEL * 2048];   // [n][k], K-major rows
__device__ __nv_bfloat16 g_Wlo[DMODEL * 2048];

// ---------------------------------------------------------------- asm helpers
__device__ __forceinline__ uint32_t smem_u32(const void* p) {
    uint32_t a;
    asm("{ .reg .u64 t; cvta.to.shared.u64 t, %1; cvt.u32.u64 %0, t; }"
        : "=r"(a) : "l"(p));
    return a;
}

__device__ __forceinline__ void cp16(uint32_t dst, const void* src) {
    asm volatile("cp.async.cg.shared.global [%0], [%1], 16;"
                 :: "r"(dst), "l"(src));
}
#define CP_COMMIT() asm volatile("cp.async.commit_group;")

__device__ __forceinline__ void ldsm4(uint32_t* r, uint32_t addr) {
    asm volatile("ldmatrix.sync.aligned.m8n8.x4.shared.b16 {%0,%1,%2,%3}, [%4];"
                 : "=r"(r[0]), "=r"(r[1]), "=r"(r[2]), "=r"(r[3]) : "r"(addr));
}

__device__ __forceinline__ void mma16816(float* c, const uint32_t* a, const uint32_t* b) {
    asm volatile(
        "mma.sync.aligned.m16n8k16.row.col.f32.bf16.bf16.f32 "
        "{%0,%1,%2,%3}, {%4,%5,%6,%7}, {%8,%9}, {%0,%1,%2,%3};"
        : "+f"(c[0]), "+f"(c[1]), "+f"(c[2]), "+f"(c[3])
        : "r"(a[0]), "r"(a[1]), "r"(a[2]), "r"(a[3]), "r"(b[0]), "r"(b[1]));
}

// ----------------------------------------------------------------------------
// conv_W: split-transpose W[2048,512] -> Whi/Wlo [n=512][k=2048] bf16.
// ----------------------------------------------------------------------------
__global__ __launch_bounds__(256) void conv_W(const float* __restrict__ W)
{
    __shared__ float tile[32][33];
    const int k0 = blockIdx.x * 32, n0 = blockIdx.y * 32;
    const int tx = threadIdx.x & 31, ty = threadIdx.x >> 5;

    #pragma unroll
    for (int r = 0; r < 4; r++) {
        int i = ty + 8 * r;
        tile[i][tx] = W[(size_t)(k0 + i) * DMODEL + n0 + tx];
    }
    __syncthreads();
    #pragma unroll
    for (int r = 0; r < 4; r++) {
        int i = ty + 8 * r;                       // n_local
        float v = tile[tx][i];                    // k_local = tx
        __nv_bfloat16 h = __float2bfloat16(v);
        __nv_bfloat16 l = __float2bfloat16(v - __bfloat162float(h));
        size_t o = (size_t)(n0 + i) * 2048 + k0 + tx;
        g_Whi[o] = h;
        g_Wlo[o] = l;
    }
}

// ----------------------------------------------------------------------------
// conv_A: split + concat + zero-pad all A sources into Ahi/Alo [2688][512].
// ----------------------------------------------------------------------------
__global__ __launch_bounds__(128) void conv_A(
    const float* __restrict__ pe,   const float* __restrict__ emb2,
    const float* __restrict__ emb1, const float* __restrict__ emb0)
{
    const int pr = blockIdx.x;
    const int t  = threadIdx.x;
    const float* src = nullptr;
    if (pr < 2048)      { src = pe + (size_t)pr * DMODEL; }
    else if (pr < 2432) { int r = pr - 2048; if (r < 288) src = emb2 + (size_t)r * DMODEL; }
    else if (pr < 2560) { int r = pr - 2432; if (r < 24)  src = emb1 + (size_t)r * DMODEL; }
    else                { int r = pr - 2560; if (r < 7)   src = emb0 + (size_t)r * DMODEL; }

    float4 v = src ? ((const float4*)src)[t] : make_float4(0.f, 0.f, 0.f, 0.f);

    __nv_bfloat16 hx = __float2bfloat16(v.x), hy = __float2bfloat16(v.y);
    __nv_bfloat16 hz = __float2bfloat16(v.z), hw = __float2bfloat16(v.w);
    __nv_bfloat16 lx = __float2bfloat16(v.x - __bfloat162float(hx));
    __nv_bfloat16 ly = __float2bfloat16(v.y - __bfloat162float(hy));
    __nv_bfloat16 lz = __float2bfloat16(v.z - __bfloat162float(hz));
    __nv_bfloat16 lw = __float2bfloat16(v.w - __bfloat162float(hw));

    uint2 ph, pl;
    ph.x = (uint32_t)__bfloat16_as_ushort(hx) | ((uint32_t)__bfloat16_as_ushort(hy) << 16);
    ph.y = (uint32_t)__bfloat16_as_ushort(hz) | ((uint32_t)__bfloat16_as_ushort(hw) << 16);
    pl.x = (uint32_t)__bfloat16_as_ushort(lx) | ((uint32_t)__bfloat16_as_ushort(ly) << 16);
    pl.y = (uint32_t)__bfloat16_as_ushort(lz) | ((uint32_t)__bfloat16_as_ushort(lw) << 16);

    ((uint2*)g_Ahi)[(size_t)pr * NV4 + t] = ph;
    ((uint2*)g_Alo)[(size_t)pr * NV4 + t] = pl;
}

// ----------------------------------------------------------------------------
// table_mma: mma.sync bf16x3 GEMM. grid (42 m-tiles, 8 n-tiles), 128 threads.
// CTA tile 64(M) x 64(N); virtual K = 1536 (3 terms x 512) in 48 k32 stages.
// cp.async 3-deep pipeline; smem rows padded to 80B (conflict-free ldmatrix).
// Warp layout 2x2, each warp 32m x 32n via m16n8k16.
// ----------------------------------------------------------------------------
#define ROWB   80
#define OPBYTES (64 * ROWB)          // 5120 per operand per stage
#define NSTAGE 3
#define NKS    48                    // 48 stages of k32

__global__ __launch_bounds__(128) void table_mma(const float* __restrict__ bias)
{
    __shared__ __align__(16) char sm[NSTAGE * 2 * OPBYTES];   // 30720 B
    const uint32_t sbase = smem_u32(sm);

    const int tid = threadIdx.x;
    const int bx = blockIdx.x, by = blockIdx.y;
    const int arow0 = bx * 64;
    const int col0  = by * 64;

    float* C; int M, segRow0, koff; bool addb = false;
    if (bx < 32)      { C = g_Tp; M = 2048; segRow0 = arow0;        koff = 1536; addb = true; }
    else if (bx < 38) { C = g_T2; M = 288;  segRow0 = arow0 - 2048; koff = 1024; }
    else if (bx < 40) { C = g_T1; M = 24;   segRow0 = arow0 - 2432; koff = 512;  }
    else              { C = g_T0; M = 7;    segRow0 = arow0 - 2560; koff = 0;    }

    // per-thread cp.async geometry: rows tid>>2 and +32, quarter q = tid&3
    const int rA = tid >> 2;
    const int q  = tid & 3;
    const uint32_t dA0 = rA * ROWB + q * 16;
    const uint32_t dA1 = (rA + 32) * ROWB + q * 16;
    const size_t aoff0 = (size_t)(arow0 + rA) * DMODEL + q * 8;
    const size_t aoff1 = aoff0 + (size_t)32 * DMODEL;
    const size_t boff0 = (size_t)(col0 + rA) * 2048 + koff + q * 8;
    const size_t boff1 = boff0 + (size_t)32 * 2048;

    // warp / lane geometry
    const int wid  = tid >> 5, lane = tid & 31;
    const int wm   = (wid & 1) * 32, wn = (wid >> 1) * 32;
    const int quad = lane >> 3, lr = lane & 7;

    // ldmatrix smem offsets (buf/kh added later)
    uint32_t offA[2], offB[2];
    #pragma unroll
    for (int mf = 0; mf < 2; mf++)
        offA[mf] = (uint32_t)(wm + mf * 16 + (quad & 1) * 8 + lr) * ROWB + (quad >> 1) * 16;
    #pragma unroll
    for (int nb = 0; nb < 2; nb++)
        offB[nb] = (uint32_t)(wn + nb * 16 + ((quad >> 1) & 1) * 8 + lr) * ROWB + (quad & 1) * 16;

    float acc[2][4][4] = {};

    // ---- stage issue: stage s -> term s>>4, k0 = (s&15)*32, buf s%3
    auto issue = [&](int s) {
        const int term = s >> 4;
        const int k0   = (s & 15) * 32;
        const __nv_bfloat16* Asrc = (term == 2) ? g_Alo : g_Ahi;
        const __nv_bfloat16* Bsrc = (term == 1) ? g_Wlo : g_Whi;
        const uint32_t sA = sbase + (uint32_t)(s % NSTAGE) * (2 * OPBYTES);
        const uint32_t sB = sA + OPBYTES;
        cp16(sA + dA0, Asrc + aoff0 + k0);
        cp16(sA + dA1, Asrc + aoff1 + k0);
        cp16(sB + dA0, Bsrc + boff0 + k0);
        cp16(sB + dA1, Bsrc + boff1 + k0);
        CP_COMMIT();
    };

    issue(0);
    issue(1);

    for (int s = 0; s < NKS; s++) {
        if (s + 2 < NKS) {
            issue(s + 2);
            asm volatile("cp.async.wait_group 2;");
        } else {
            asm volatile("cp.async.wait_group 0;");
        }
        __syncthreads();

        const uint32_t sA = sbase + (uint32_t)(s % NSTAGE) * (2 * OPBYTES);
        const uint32_t sB = sA + OPBYTES;

        #pragma unroll
        for (int kh = 0; kh < 2; kh++) {          // two k16 steps per k32 stage
            uint32_t a[2][4], b[2][4];
            ldsm4(a[0], sA + offA[0] + kh * 32);
            ldsm4(a[1], sA + offA[1] + kh * 32);
            ldsm4(b[0], sB + offB[0] + kh * 32);
            ldsm4(b[1], sB + offB[1] + kh * 32);
            #pragma unroll
            for (int mf = 0; mf < 2; mf++) {
                mma16816(acc[mf][0], a[mf], &b[0][0]);   // n 0-7
                mma16816(acc[mf][1], a[mf], &b[0][2]);   // n 8-15
                mma16816(acc[mf][2], a[mf], &b[1][0]);   // n 16-23
                mma16816(acc[mf][3], a[mf], &b[1][2]);   // n 24-31
            }
        }
        __syncthreads();
    }

    // ---- epilogue: c-frag thread t -> rows t/4, t/4+8 ; cols 2(t%4)
    const int erow = lane >> 2;
    const int ecol = (lane & 3) * 2;

    float2 bb[4];
    #pragma unroll
    for (int nf = 0; nf < 4; nf++) {
        if (addb) {
            const int n = col0 + wn + nf * 8 + ecol;
            bb[nf].x = bias[n];
            bb[nf].y = bias[n + 1];
        } else {
            bb[nf].x = 0.f; bb[nf].y = 0.f;
        }
    }

    #pragma unroll
    for (int mf = 0; mf < 2; mf++) {
        const int m0 = segRow0 + wm + mf * 16 + erow;
        #pragma unroll
        for (int nf = 0; nf < 4; nf++) {
            const int n = col0 + wn + nf * 8 + ecol;
            if (m0 < M) {
                float2 v = make_float2(acc[mf][nf][0] + bb[nf].x,
                                       acc[mf][nf][1] + bb[nf].y);
                *(float2*)&C[(size_t)m0 * DMODEL + n] = v;
            }
            if (m0 + 8 < M) {
                float2 v = make_float2(acc[mf][nf][2] + bb[nf].x,
                                       acc[mf][nf][3] + bb[nf].y);
                *(float2*)&C[(size_t)(m0 + 8) * DMODEL + n] = v;
            }
        }
    }
}

// ----------------------------------------------------------------------------
// combine01: T01[i*24+j] = T0[i] + T1[j].
// ----------------------------------------------------------------------------
__global__ __launch_bounds__(128) void combine01()
{
    const int r = blockIdx.x, t = threadIdx.x;
    const int i = r / 24, j = r % 24;
    float4 a = ((const float4*)g_T0)[i * NV4 + t];
    float4 b = ((const float4*)g_T1)[j * NV4 + t];
    float4 v;
    v.x = a.x + b.x; v.y = a.y + b.y; v.z = a.z + b.z; v.w = a.w + b.w;
    ((float4*)g_T01)[r * NV4 + t] = v;
}

// ----------------------------------------------------------------------------
// gather_add: out = T01 + T2 + Tp.  grid (2048, 2), 128 threads.
// ----------------------------------------------------------------------------
__global__ __launch_bounds__(128) void gather_add(
    const int* __restrict__ in0, const int* __restrict__ tg0,
    const int* __restrict__ in1, const int* __restrict__ tg1,
    const int* __restrict__ in2, const int* __restrict__ tg2,
    float* __restrict__ out)
{
    const int l = blockIdx.x, o = blockIdx.y, t = threadIdx.x;

    __shared__ int sidx[3][BATCH];
    if (t < 96) {
        int which = t >> 5, b = t & 31;
        const int* p = (which == 0) ? (o ? tg0 : in0)
                     : (which == 1) ? (o ? tg1 : in1)
                                    : (o ? tg2 : in2);
        sidx[which][b] = p[b * PLEN + l];
    }
    __syncthreads();

    const float4* __restrict__ T01 = (const float4*)g_T01;
    const float4* __restrict__ T2  = (const float4*)g_T2;
    const float4 tp = ((const float4*)g_Tp)[l * NV4 + t];

    float4* o4 = (float4*)out + ((size_t)o * BATCH * PLEN + l) * NV4 + t;

    #pragma unroll 4
    for (int b = 0; b < BATCH; b++) {
        const int i01 = sidx[0][b] * 24 + sidx[1][b];
        const int i2  = sidx[2][b];
        float4 a = T01[i01 * NV4 + t];
        float4 d = T2 [i2  * NV4 + t];
        float4 v;
        v.x = tp.x + a.x + d.x;
        v.y = tp.y + a.y + d.y;
        v.z = tp.z + a.z + d.z;
        v.w = tp.w + a.w + d.w;
        __stcs(o4 + (size_t)b * PLEN * NV4, v);
    }
}

// ----------------------------------------------------------------------------
// Launch. Inputs (metadata order):
//  0..5: in0,tg0,in1,tg1,in2,tg2 int32 [32,2048]
//  6:emb0[7,512] 7:emb1[24,512] 8:emb2[288,512] 9:pe[4096,512]
//  10:W[2048,512] 11:b[512]       output: float32 [2,32,2048,512]
// ----------------------------------------------------------------------------
extern "C" void kernel_launch(void* const* d_in, const int* in_sizes, int n_in,
                              void* d_out, int out_size)
{
    const int*   in0  = (const int*)  d_in[0];
    const int*   tg0  = (const int*)  d_in[1];
    const int*   in1  = (const int*)  d_in[2];
    const int*   tg1  = (const int*)  d_in[3];
    const int*   in2  = (const int*)  d_in[4];
    const int*   tg2  = (const int*)  d_in[5];
    const float* emb0 = (const float*)d_in[6];
    const float* emb1 = (const float*)d_in[7];
    const float* emb2 = (const float*)d_in[8];
    const float* pe   = (const float*)d_in[9];
    const float* W    = (const float*)d_in[10];
    const float* bias = (const float*)d_in[11];
    float* out = (float*)d_out;

    conv_W<<<dim3(64, 16), 256>>>(W);
    conv_A<<<APAD, 128>>>(pe, emb2, emb1, emb0);
    table_mma<<<dim3(42, 8), 128>>>(bias);
    combine01<<<168, 128>>>();
    gather_add<<<dim3(PLEN, 2), 128>>>(in0, tg0, in1, tg1, in2, tg2, out);
}